// round 2
// baseline (speedup 1.0000x reference)
#include <cuda_runtime.h>
#include <math.h>

#define BATCH   8
#define NPTS    4096
#define TILE    256
#define BLOCK   256
#define QPB     (BLOCK * 2)   // queries per block (2 per thread, packed f32x2)

// Scratch accumulators: [dir][batch]
__device__ double g_accum[2 * BATCH];

__global__ void zero_accum_kernel() {
    int i = threadIdx.x;
    if (i < 2 * BATCH) g_accum[i] = 0.0;
}

static __device__ __forceinline__ unsigned long long pack2(float a, float b) {
    unsigned long long r;
    asm("mov.b64 %0, {%1, %2};" : "=l"(r) : "f"(a), "f"(b));
    return r;
}
static __device__ __forceinline__ unsigned long long fma2(
    unsigned long long a, unsigned long long b, unsigned long long c) {
    unsigned long long r;
    asm("fma.rn.f32x2 %0, %1, %2, %3;" : "=l"(r) : "l"(a), "l"(b), "l"(c));
    return r;
}
static __device__ __forceinline__ void unpack2(unsigned long long v, float& lo, float& hi) {
    asm("mov.b64 {%0, %1}, %2;" : "=f"(lo), "=f"(hi) : "l"(v));
}

// dir 0: query = x, database = y  -> pc1
// dir 1: query = y, database = x  -> pc2
// Each thread owns 2 query points packed as f32x2. Argmin objective:
// h - q.c  with h = 0.5*|c|^2  (per-query |q|^2 constant dropped — argmin-invariant).
__global__ void __launch_bounds__(BLOCK) chamfer_kernel(
    const float* __restrict__ x, const float* __restrict__ y)
{
    const int dir = blockIdx.z;
    const int b   = blockIdx.y;
    const float* q  = (dir == 0) ? x : y;
    const float* db = (dir == 0) ? y : x;
    const float* qb  = q  + (size_t)b * NPTS * 3;
    const float* dbb = db + (size_t)b * NPTS * 3;

    const int i0 = blockIdx.x * QPB + threadIdx.x;
    const int i1 = i0 + BLOCK;

    const float q0x = qb[i0 * 3 + 0], q0y = qb[i0 * 3 + 1], q0z = qb[i0 * 3 + 2];
    const float q1x = qb[i1 * 3 + 0], q1y = qb[i1 * 3 + 1], q1z = qb[i1 * 3 + 2];

    const unsigned long long nqx = pack2(-q0x, -q1x);
    const unsigned long long nqy = pack2(-q0y, -q1y);
    const unsigned long long nqz = pack2(-q0z, -q1z);

    // Duplicated candidate layout: per candidate j, 32 bytes:
    //   sh[2j]   = { (cx,cx), (cy,cy) }
    //   sh[2j+1] = { (cz,cz), (h ,h ) }
    __shared__ ulonglong2 sh[TILE * 2];

    float best0 = 3.4e38f, best1 = 3.4e38f;
    int   bi0 = 0, bi1 = 0;

    for (int t = 0; t < NPTS; t += TILE) {
        __syncthreads();
        {
            const int c = t + threadIdx.x;
            float cx = dbb[c * 3 + 0];
            float cy = dbb[c * 3 + 1];
            float cz = dbb[c * 3 + 2];
            float h  = 0.5f * fmaf(cx, cx, fmaf(cy, cy, cz * cz));
            ulonglong2 A, Bv;
            A.x  = pack2(cx, cx);  A.y  = pack2(cy, cy);
            Bv.x = pack2(cz, cz);  Bv.y = pack2(h, h);
            sh[2 * threadIdx.x + 0] = A;
            sh[2 * threadIdx.x + 1] = Bv;
        }
        __syncthreads();

        #pragma unroll 16
        for (int j = 0; j < TILE; j++) {
            // Broadcast LDS.128 x2 (all lanes same address, conflict-free).
            ulonglong2 A  = sh[2 * j + 0];
            ulonglong2 Bv = sh[2 * j + 1];
            unsigned long long acc = fma2(nqz, Bv.x, Bv.y); // h - qz*cz
            acc = fma2(nqy, A.y, acc);                      // - qy*cy
            acc = fma2(nqx, A.x, acc);                      // - qx*cx
            float d0, d1;
            unpack2(acc, d0, d1);
            const int jj = t + j;
            // Strict < keeps FIRST minimum -> matches jnp.argmin tie-breaking.
            bool p0 = d0 < best0;  best0 = fminf(best0, d0);  bi0 = p0 ? jj : bi0;
            bool p1 = d1 < best1;  best1 = fminf(best1, d1);  bi1 = p1 ? jj : bi1;
        }
    }

    // Gather NN coords, compute sum_c |diff_c|^5 for both queries (exact values,
    // independent of the reduced-form scores used for the argmin).
    float v;
    {
        float nx = dbb[bi0 * 3 + 0], ny = dbb[bi0 * 3 + 1], nz = dbb[bi0 * 3 + 2];
        float ax = fabsf(q0x - nx), ay = fabsf(q0y - ny), az = fabsf(q0z - nz);
        float ax2 = ax * ax, ay2 = ay * ay, az2 = az * az;
        v = ax2 * ax2 * ax + ay2 * ay2 * ay + az2 * az2 * az;

        nx = dbb[bi1 * 3 + 0]; ny = dbb[bi1 * 3 + 1]; nz = dbb[bi1 * 3 + 2];
        ax = fabsf(q1x - nx); ay = fabsf(q1y - ny); az = fabsf(q1z - nz);
        ax2 = ax * ax; ay2 = ay * ay; az2 = az * az;
        v += ax2 * ax2 * ax + ay2 * ay2 * ay + az2 * az2 * az;
    }

    __shared__ float red[BLOCK];
    red[threadIdx.x] = v;
    __syncthreads();
    #pragma unroll
    for (int stride = BLOCK / 2; stride >= 32; stride >>= 1) {
        if (threadIdx.x < stride) red[threadIdx.x] += red[threadIdx.x + stride];
        __syncthreads();
    }
    if (threadIdx.x < 32) {
        float r = red[threadIdx.x];
        #pragma unroll
        for (int off = 16; off > 0; off >>= 1)
            r += __shfl_down_sync(0xFFFFFFFF, r, off);
        if (threadIdx.x == 0)
            atomicAdd(&g_accum[dir * BATCH + b], (double)r);
    }
}

__global__ void final_kernel(float* __restrict__ out) {
    if (threadIdx.x == 0) {
        double acc = 0.0;
        for (int b = 0; b < BATCH; b++) {
            acc += pow(g_accum[b], 0.2);          // pnorm(pc1) for batch b
            acc += pow(g_accum[BATCH + b], 0.2);  // pnorm(pc2) for batch b
        }
        out[0] = (float)(acc / (double)BATCH);
    }
}

extern "C" void kernel_launch(void* const* d_in, const int* in_sizes, int n_in,
                              void* d_out, int out_size)
{
    const float* x = (const float*)d_in[0];
    const float* y = (const float*)d_in[1];
    float* out = (float*)d_out;

    zero_accum_kernel<<<1, 32>>>();

    dim3 grid(NPTS / QPB, BATCH, 2);   // 8 x 8 x 2 = 128 blocks
    chamfer_kernel<<<grid, BLOCK>>>(x, y);

    final_kernel<<<1, 32>>>(out);
}

// round 3
// speedup vs baseline: 1.2256x; 1.2256x over previous
#include <cuda_runtime.h>
#include <math.h>

#define BATCH   8
#define NPTS    4096
#define TILE    256
#define BLOCK   128
#define CHUNKS  (NPTS / BLOCK)   // 32

// Scratch accumulators: [dir][batch]
__device__ double g_accum[2 * BATCH];

__global__ void zero_accum_kernel() {
    int i = threadIdx.x;
    if (i < 2 * BATCH) g_accum[i] = 0.0;
}

// dir 0: query = x, database = y  -> pc1
// dir 1: query = y, database = x  -> pc2
// Argmin objective: h - q.c  with h = 0.5*|c|^2 (per-query |q|^2 dropped,
// argmin-invariant). Candidates cached in shared as float4 (cx,cy,cz,h)
// -> inner loop = 1 broadcast LDS.128 + 3 FFMA + compare/select.
__global__ void __launch_bounds__(BLOCK) chamfer_kernel(
    const float* __restrict__ x, const float* __restrict__ y)
{
    const int dir = blockIdx.z;
    const int b   = blockIdx.y;
    const float* q  = (dir == 0) ? x : y;
    const float* db = (dir == 0) ? y : x;
    const float* qb  = q  + (size_t)b * NPTS * 3;
    const float* dbb = db + (size_t)b * NPTS * 3;

    const int i = blockIdx.x * BLOCK + threadIdx.x;

    const float qx = qb[i * 3 + 0];
    const float qy = qb[i * 3 + 1];
    const float qz = qb[i * 3 + 2];
    const float nqx = -qx, nqy = -qy, nqz = -qz;

    __shared__ float4 sh[TILE];

    float best = 3.4e38f;
    int   bi   = 0;

    for (int t = 0; t < NPTS; t += TILE) {
        __syncthreads();
        // Each of 128 threads preps 2 of the 256 tile candidates.
        #pragma unroll
        for (int k = 0; k < TILE / BLOCK; k++) {
            const int c  = t + threadIdx.x + k * BLOCK;
            const int cl = threadIdx.x + k * BLOCK;
            float cx = dbb[c * 3 + 0];
            float cy = dbb[c * 3 + 1];
            float cz = dbb[c * 3 + 2];
            float h  = 0.5f * fmaf(cx, cx, fmaf(cy, cy, cz * cz));
            sh[cl] = make_float4(cx, cy, cz, h);
        }
        __syncthreads();

        #pragma unroll 16
        for (int j = 0; j < TILE; j++) {
            float4 c = sh[j];               // broadcast LDS.128, conflict-free
            float d = fmaf(nqx, c.x, fmaf(nqy, c.y, fmaf(nqz, c.z, c.w)));
            const int jj = t + j;
            // Strict < keeps FIRST minimum -> matches jnp.argmin tie-breaking.
            bool p = d < best;
            best = fminf(best, d);
            bi   = p ? jj : bi;
        }
    }

    // Gather NN coords, compute exact sum_c |diff_c|^5 (independent of the
    // reduced-form score used for the argmin).
    float nx = dbb[bi * 3 + 0];
    float ny = dbb[bi * 3 + 1];
    float nz = dbb[bi * 3 + 2];
    float ax = fabsf(qx - nx), ay = fabsf(qy - ny), az = fabsf(qz - nz);
    float ax2 = ax * ax, ay2 = ay * ay, az2 = az * az;
    float v = ax2 * ax2 * ax + ay2 * ay2 * ay + az2 * az2 * az;

    // Block reduction of v.
    __shared__ float red[BLOCK];
    red[threadIdx.x] = v;
    __syncthreads();
    #pragma unroll
    for (int stride = BLOCK / 2; stride >= 32; stride >>= 1) {
        if (threadIdx.x < stride) red[threadIdx.x] += red[threadIdx.x + stride];
        __syncthreads();
    }
    if (threadIdx.x < 32) {
        float r = red[threadIdx.x];
        #pragma unroll
        for (int off = 16; off > 0; off >>= 1)
            r += __shfl_down_sync(0xFFFFFFFF, r, off);
        if (threadIdx.x == 0)
            atomicAdd(&g_accum[dir * BATCH + b], (double)r);
    }
}

__global__ void final_kernel(float* __restrict__ out) {
    if (threadIdx.x == 0) {
        double acc = 0.0;
        for (int b = 0; b < BATCH; b++) {
            acc += pow(g_accum[b], 0.2);          // pnorm(pc1) for batch b
            acc += pow(g_accum[BATCH + b], 0.2);  // pnorm(pc2) for batch b
        }
        out[0] = (float)(acc / (double)BATCH);
    }
}

extern "C" void kernel_launch(void* const* d_in, const int* in_sizes, int n_in,
                              void* d_out, int out_size)
{
    const float* x = (const float*)d_in[0];
    const float* y = (const float*)d_in[1];
    float* out = (float*)d_out;

    zero_accum_kernel<<<1, 32>>>();

    dim3 grid(CHUNKS, BATCH, 2);   // 32 x 8 x 2 = 512 blocks
    chamfer_kernel<<<grid, BLOCK>>>(x, y);

    final_kernel<<<1, 32>>>(out);
}

// round 4
// speedup vs baseline: 1.4116x; 1.1517x over previous
#include <cuda_runtime.h>
#include <math.h>

#define BATCH   8
#define NPTS    4096
#define SPLITS  4
#define SCAND   (NPTS / SPLITS)   // 1024 candidates per split
#define TILE    256
#define BLOCK   64
#define Q       4
#define QPB     (BLOCK * Q)       // 256 queries per block

// Scratch (static device arrays; no allocation allowed)
__device__ double g_accum[2 * BATCH];
__device__ float  g_pbest[2 * BATCH * NPTS * SPLITS];
__device__ int    g_pidx [2 * BATCH * NPTS * SPLITS];

__global__ void zero_accum_kernel() {
    int i = threadIdx.x;
    if (i < 2 * BATCH) g_accum[i] = 0.0;
}

// Bit-exact rescore used by both the rescan and (implicitly) the main loop.
static __device__ __forceinline__ float score(float cx, float cy, float cz,
                                              float nqx, float nqy, float nqz) {
    float h = 0.5f * fmaf(cx, cx, fmaf(cy, cy, cz * cz));
    return fmaf(nqx, cx, fmaf(nqy, cy, fmaf(nqz, cz, h)));
}

static __device__ __forceinline__ int rescan32(const float* __restrict__ dbb, int base,
                                               float nqx, float nqy, float nqz, float best) {
    for (int j = 0; j < 32; j++) {
        int c = base + j;
        float d = score(dbb[c * 3 + 0], dbb[c * 3 + 1], dbb[c * 3 + 2], nqx, nqy, nqz);
        if (d == best) return c;   // first exact match = first min occurrence
    }
    return base;  // unreachable
}

// Each thread: 4 queries, scanning this block's candidate split.
// Argmin objective: h - q.c, h = 0.5|c|^2 (|q|^2 dropped, argmin-invariant).
__global__ void __launch_bounds__(BLOCK) chamfer_main(
    const float* __restrict__ x, const float* __restrict__ y)
{
    const int qchunk = blockIdx.x >> 2;   // 0..15
    const int split  = blockIdx.x & 3;    // 0..3
    const int b   = blockIdx.y;
    const int dir = blockIdx.z;
    const float* q  = (dir == 0) ? x : y;
    const float* db = (dir == 0) ? y : x;
    const float* qb  = q  + (size_t)b * NPTS * 3;
    const float* dbb = db + (size_t)b * NPTS * 3;

    const int i0 = qchunk * QPB + threadIdx.x;
    const int i1 = i0 + BLOCK;
    const int i2 = i0 + 2 * BLOCK;
    const int i3 = i0 + 3 * BLOCK;

    const float nqx0 = -qb[i0*3+0], nqy0 = -qb[i0*3+1], nqz0 = -qb[i0*3+2];
    const float nqx1 = -qb[i1*3+0], nqy1 = -qb[i1*3+1], nqz1 = -qb[i1*3+2];
    const float nqx2 = -qb[i2*3+0], nqy2 = -qb[i2*3+1], nqz2 = -qb[i2*3+2];
    const float nqx3 = -qb[i3*3+0], nqy3 = -qb[i3*3+1], nqz3 = -qb[i3*3+2];

    __shared__ float4 sh[TILE];

    float best0 = 3.4e38f, best1 = 3.4e38f, best2 = 3.4e38f, best3 = 3.4e38f;
    const int cbeg = split * SCAND;
    int base0 = cbeg, base1 = cbeg, base2 = cbeg, base3 = cbeg;

    for (int t = 0; t < SCAND; t += TILE) {
        __syncthreads();
        #pragma unroll
        for (int k = 0; k < TILE / BLOCK; k++) {
            const int cl = threadIdx.x + k * BLOCK;
            const int c  = cbeg + t + cl;
            float cx = dbb[c*3+0], cy = dbb[c*3+1], cz = dbb[c*3+2];
            sh[cl] = make_float4(cx, cy, cz, 0.5f * fmaf(cx, cx, fmaf(cy, cy, cz * cz)));
        }
        __syncthreads();

        #pragma unroll
        for (int g = 0; g < TILE / 32; g++) {
            const float p0 = best0, p1 = best1, p2 = best2, p3 = best3;
            #pragma unroll 8
            for (int j = 0; j < 32; j++) {
                float4 c = sh[g * 32 + j];   // broadcast LDS.128
                best0 = fminf(best0, fmaf(nqx0, c.x, fmaf(nqy0, c.y, fmaf(nqz0, c.z, c.w))));
                best1 = fminf(best1, fmaf(nqx1, c.x, fmaf(nqy1, c.y, fmaf(nqz1, c.z, c.w))));
                best2 = fminf(best2, fmaf(nqx2, c.x, fmaf(nqy2, c.y, fmaf(nqz2, c.z, c.w))));
                best3 = fminf(best3, fmaf(nqx3, c.x, fmaf(nqy3, c.y, fmaf(nqz3, c.z, c.w))));
            }
            const int gb = cbeg + t + g * 32;
            // Strict < keeps the EARLIEST group containing the running min.
            if (best0 < p0) base0 = gb;
            if (best1 < p1) base1 = gb;
            if (best2 < p2) base2 = gb;
            if (best3 < p3) base3 = gb;
        }
    }

    // Recover exact indices (bit-exact recompute within the recorded group).
    const int idx0 = rescan32(dbb, base0, nqx0, nqy0, nqz0, best0);
    const int idx1 = rescan32(dbb, base1, nqx1, nqy1, nqz1, best1);
    const int idx2 = rescan32(dbb, base2, nqx2, nqy2, nqz2, best2);
    const int idx3 = rescan32(dbb, base3, nqx3, nqy3, nqz3, best3);

    const int qs = (dir * BATCH + b) * NPTS;
    g_pbest[(qs + i0) * SPLITS + split] = best0;  g_pidx[(qs + i0) * SPLITS + split] = idx0;
    g_pbest[(qs + i1) * SPLITS + split] = best1;  g_pidx[(qs + i1) * SPLITS + split] = idx1;
    g_pbest[(qs + i2) * SPLITS + split] = best2;  g_pidx[(qs + i2) * SPLITS + split] = idx2;
    g_pbest[(qs + i3) * SPLITS + split] = best3;  g_pidx[(qs + i3) * SPLITS + split] = idx3;
}

// One block per 256 queries of one (dir, b): pick winning split, gather NN,
// accumulate sum |diff|^5.
__global__ void __launch_bounds__(256) combine_kernel(
    const float* __restrict__ x, const float* __restrict__ y)
{
    const int b   = blockIdx.y;
    const int dir = blockIdx.z;
    const int qi  = blockIdx.x * 256 + threadIdx.x;
    const float* q  = (dir == 0) ? x : y;
    const float* db = (dir == 0) ? y : x;
    const float* qb  = q  + (size_t)b * NPTS * 3;
    const float* dbb = db + (size_t)b * NPTS * 3;

    const int slot = ((dir * BATCH + b) * NPTS + qi) * SPLITS;
    float bb = g_pbest[slot];
    int   bi = g_pidx[slot];
    #pragma unroll
    for (int s = 1; s < SPLITS; s++) {
        float v = g_pbest[slot + s];   // strict < : earlier split wins ties
        if (v < bb) { bb = v; bi = g_pidx[slot + s]; }
    }

    float qx = qb[qi*3+0], qy = qb[qi*3+1], qz = qb[qi*3+2];
    float nx = dbb[bi*3+0], ny = dbb[bi*3+1], nz = dbb[bi*3+2];
    float ax = fabsf(qx - nx), ay = fabsf(qy - ny), az = fabsf(qz - nz);
    float ax2 = ax * ax, ay2 = ay * ay, az2 = az * az;
    float v = ax2 * ax2 * ax + ay2 * ay2 * ay + az2 * az2 * az;

    __shared__ float red[256];
    red[threadIdx.x] = v;
    __syncthreads();
    #pragma unroll
    for (int stride = 128; stride >= 32; stride >>= 1) {
        if (threadIdx.x < stride) red[threadIdx.x] += red[threadIdx.x + stride];
        __syncthreads();
    }
    if (threadIdx.x < 32) {
        float r = red[threadIdx.x];
        #pragma unroll
        for (int off = 16; off > 0; off >>= 1)
            r += __shfl_down_sync(0xFFFFFFFF, r, off);
        if (threadIdx.x == 0)
            atomicAdd(&g_accum[dir * BATCH + b], (double)r);
    }
}

__global__ void final_kernel(float* __restrict__ out) {
    if (threadIdx.x == 0) {
        double acc = 0.0;
        for (int b = 0; b < BATCH; b++) {
            acc += pow(g_accum[b], 0.2);
            acc += pow(g_accum[BATCH + b], 0.2);
        }
        out[0] = (float)(acc / (double)BATCH);
    }
}

extern "C" void kernel_launch(void* const* d_in, const int* in_sizes, int n_in,
                              void* d_out, int out_size)
{
    const float* x = (const float*)d_in[0];
    const float* y = (const float*)d_in[1];
    float* out = (float*)d_out;

    zero_accum_kernel<<<1, 32>>>();

    dim3 grid(16 * SPLITS, BATCH, 2);   // 64 x 8 x 2 = 1024 blocks
    chamfer_main<<<grid, BLOCK>>>(x, y);

    dim3 cgrid(NPTS / 256, BATCH, 2);   // 16 x 8 x 2 = 256 blocks
    combine_kernel<<<cgrid, 256>>>(x, y);

    final_kernel<<<1, 32>>>(out);
}